// round 16
// baseline (speedup 1.0000x reference)
#include <cuda_runtime.h>
#include <cuda_bf16.h>

// ---------------------------------------------------------------------------
// Ptychography forward model (sm_103a).  Fused 1-D FFT passes; FFT-256 =
// 16x16 four-step in packed fp32x2; in-place digit-reversed FFT-16; merged
// final exchange+transpose; tree cross-twiddles; kP1 split (39-tile Fy dedup);
// L1 prefetches; kFinal mode-split + deterministic reduce; PDL chain.
// R16: merged-tail smem reads vectorized to LDS.128 (ulonglong2); setup
// kernels fused (one fewer PDL boundary).
// ---------------------------------------------------------------------------

typedef unsigned long long cpk;   // packed complex: lo=re, hi=im (f32x2)

// ---- static device scratch ----
__device__ cpk   g_g[39 * 65536];        // probe tiles after first Fx
__device__ cpk   g_h[39 * 65536];        // probe tiles after Fy (spectrum)
__device__ cpk   g_psiA[256 * 65536];    // ping (128 MB)
__device__ cpk   g_psiB[256 * 65536];    // pong (128 MB)
__device__ cpk   g_tf[65536];            // angular-spectrum TF (pre-scaled 1/65536)
__device__ float g_part[4 * 32 * 65536]; // per-mode-group intensity partials (32 MB)
__device__ int2  g_ipos[32];
__device__ float2 g_frac[32];
__device__ float g_w[32][4];

// ---- packed complex helpers ----
__device__ __forceinline__ cpk mkpk(float x, float y) {
    cpk r; asm("mov.b64 %0, {%1, %2};" : "=l"(r) : "f"(x), "f"(y)); return r;
}
__device__ __forceinline__ void unpk(cpk a, float& x, float& y) {
    asm("mov.b64 {%0, %1}, %2;" : "=f"(x), "=f"(y) : "l"(a));
}
__device__ __forceinline__ cpk addpk(cpk a, cpk b) {
    cpk r; asm("add.rn.f32x2 %0, %1, %2;" : "=l"(r) : "l"(a), "l"(b)); return r;
}
__device__ __forceinline__ cpk fmapk(cpk a, cpk b, cpk c) {
    cpk r; asm("fma.rn.f32x2 %0, %1, %2, %3;" : "=l"(r) : "l"(a), "l"(b), "l"(c)); return r;
}
__device__ __forceinline__ cpk subpk(cpk a, cpk b, cpk n1) {   // a - b
    return fmapk(b, n1, a);
}
__device__ __forceinline__ cpk cmulpp(cpk a, cpk b) {          // a * b
    float ax, ay, bx, by; unpk(a, ax, ay); unpk(b, bx, by);
    return mkpk(fmaf(ax, bx, -(ay * by)), fmaf(ax, by, ay * bx));
}
__device__ __forceinline__ cpk cmulcc(cpk a, cpk b) {          // a * conj(b)
    float ax, ay, bx, by; unpk(a, ax, ay); unpk(b, bx, by);
    return mkpk(fmaf(ax, bx, ay * by), fmaf(ay, bx, -(ax * by)));
}
__device__ __forceinline__ cpk cmulk(cpk a, float bx, float by) { // a * (bx+i by)
    float ax, ay; unpk(a, ax, ay);
    return mkpk(fmaf(ax, bx, -(ay * by)), fmaf(ax, by, ay * bx));
}

__device__ __forceinline__ void pf_l1(const void* p) {
    asm volatile("prefetch.global.L1 [%0];" :: "l"(p));
}

// PDL: wait for predecessor's memory, then release our successor's launch.
__device__ __forceinline__ void pdl_sync_and_release() {
    cudaGridDependencySynchronize();
    cudaTriggerProgrammaticLaunchCompletion();
}

// base-4 digit reversal of 4-bit index (involution)
__device__ __forceinline__ constexpr int dr4(int p) { return ((p & 3) << 2) | (p >> 2); }

template<bool INV>
__device__ __forceinline__ void btf4p(cpk& a, cpk& b, cpk& c, cpk& d, cpk n1) {
    cpk t0 = addpk(a, c), t1 = subpk(a, c, n1);
    cpk t2 = addpk(b, d), t3 = subpk(b, d, n1);
    a = addpk(t0, t2); c = subpk(t0, t2, n1);
    float x, y; unpk(t3, x, y);
    cpk u = INV ? mkpk(-y, x) : mkpk(y, -x);   // -/+ i*t3
    b = addpk(t1, u); d = subpk(t1, u, n1);
}

#define TWK(q, arr_c, arr_s) arr_c[q], (INV ? -arr_s[q] : arr_s[q])

// in-place 16-pt DFT, NATURAL input -> DIGIT-REVERSED output (pos holds k=dr(pos))
template<bool INV>
__device__ __forceinline__ void fftDR(cpk* v, cpk n1) {
    const float C1[4] = { 1.f, 0.92387953f, 0.70710678f, 0.38268343f };
    const float S1[4] = { 0.f, -0.38268343f, -0.70710678f, -0.92387953f };
    const float C2[4] = { 1.f, 0.70710678f, 0.f, -0.70710678f };
    const float S2[4] = { 0.f, -0.70710678f, -1.f, -0.70710678f };
    const float C3[4] = { 1.f, 0.38268343f, -0.70710678f, -0.92387953f };
    const float S3[4] = { 0.f, -0.92387953f, -0.70710678f, 0.38268343f };
#pragma unroll
    for (int a = 0; a < 4; a++)
        btf4p<INV>(v[a], v[a + 4], v[a + 8], v[a + 12], n1);
#pragma unroll
    for (int q = 0; q < 4; q++) {
        if (q) {
            v[4 * q + 1] = cmulk(v[4 * q + 1], TWK(q, C1, S1));
            v[4 * q + 2] = cmulk(v[4 * q + 2], TWK(q, C2, S2));
            v[4 * q + 3] = cmulk(v[4 * q + 3], TWK(q, C3, S3));
        }
        btf4p<INV>(v[4 * q], v[4 * q + 1], v[4 * q + 2], v[4 * q + 3], n1);
    }
}

// in-place 16-pt DFT, DIGIT-REVERSED input (pos holds x[dr(pos)]) -> NATURAL out
template<bool INV>
__device__ __forceinline__ void fftRD(cpk* v, cpk n1) {
    const float C1[4] = { 1.f, 0.92387953f, 0.70710678f, 0.38268343f };
    const float S1[4] = { 0.f, -0.38268343f, -0.70710678f, -0.92387953f };
    const float C2[4] = { 1.f, 0.70710678f, 0.f, -0.70710678f };
    const float S2[4] = { 0.f, -0.70710678f, -1.f, -0.70710678f };
    const float C3[4] = { 1.f, 0.38268343f, -0.70710678f, -0.92387953f };
    const float S3[4] = { 0.f, -0.92387953f, -0.70710678f, 0.38268343f };
#pragma unroll
    for (int a = 0; a < 4; a++)
        btf4p<INV>(v[4 * a], v[4 * a + 1], v[4 * a + 2], v[4 * a + 3], n1);
#pragma unroll
    for (int q = 0; q < 4; q++) {
        if (q) {
            v[q + 4]  = cmulk(v[q + 4],  TWK(q, C1, S1));
            v[q + 8]  = cmulk(v[q + 8],  TWK(q, C2, S2));
            v[q + 12] = cmulk(v[q + 12], TWK(q, C3, S3));
        }
        btf4p<INV>(v[q], v[q + 4], v[q + 8], v[q + 12], n1);
    }
}

// Tree-structured cross-twiddle: v[k] *= W^{s*k}, k = 4a+b (powers inline).
template<bool INV, bool DRIDX>
__device__ __forceinline__ void twiddle16(cpk* v, cpk ws) {
    cpk w2 = cmulpp(ws, ws);
    cpk w3 = cmulpp(w2, ws);
    cpk g1 = cmulpp(w2, w2);        // W^4
    cpk g2 = cmulpp(g1, g1);        // W^8
    cpk g3 = cmulpp(g2, g1);        // W^12
#pragma unroll
    for (int k = 1; k < 16; k++) {
        int pos = DRIDX ? dr4(k) : k;
        int b = k & 3, a = k >> 2;
        if (b) {
            cpk wb = (b == 1) ? ws : (b == 2) ? w2 : w3;
            v[pos] = INV ? cmulcc(v[pos], wb) : cmulpp(v[pos], wb);
        }
        if (a) {
            cpk g = (a == 1) ? g1 : (a == 2) ? g2 : g3;
            v[pos] = INV ? cmulcc(v[pos], g) : cmulpp(v[pos], g);
        }
    }
}

// Full 256-pt transform, natural in -> DR out (e = s + 16*dr4(pos)).
template<bool INV>
__device__ __forceinline__ void transformA(cpk* v, cpk* xch, cpk ws,
                                           int s, cpk n1) {
    fftDR<INV>(v, n1);                       // v[pos] = comp k2 = dr(pos)
    twiddle16<INV, true>(v, ws);
    __syncwarp();
#pragma unroll
    for (int pos = 0; pos < 16; pos++)
        xch[s * 16 + ((dr4(pos) + s) & 15)] = v[pos];
    __syncwarp();
#pragma unroll
    for (int a = 0; a < 16; a++) v[a] = xch[a * 16 + ((s + a) & 15)];
    fftDR<INV>(v, n1);                       // DR out
}

// Heads of merged transforms: fft + tree twiddle, no exchange.
template<bool INV>
__device__ __forceinline__ void headB(cpk* v, cpk ws, cpk n1) {
    fftRD<INV>(v, n1);                       // natural k2 at pos
    twiddle16<INV, false>(v, ws);
}
template<bool INV>
__device__ __forceinline__ void headA(cpk* v, cpk ws, cpk n1) {
    fftDR<INV>(v, n1);                       // k2 = dr4(pos)
    twiddle16<INV, true>(v, ws);
}

// Merged-exchange smem layout: row (k2*16 + line), stride 18 cpk.
// Row base = tid*18 cpk = tid*144 B (16B-aligned) -> vectorizable reads.
#define MROW 18
#define BUFSZ (256 * MROW)

// Vectorized merged-tail read: 16 consecutive cpk as 8 x LDS.128.
__device__ __forceinline__ void tail_read(cpk* w, const cpk* row) {
    const ulonglong2* bp = (const ulonglong2*)row;
#pragma unroll
    for (int a = 0; a < 8; a++) {
        ulonglong2 t = bp[a];
        w[2 * a] = t.x; w[2 * a + 1] = t.y;
    }
}

// per-thread W256^s
__device__ __forceinline__ cpk make_ws(int s) {
    float sv, cv; sincospif(-(float)s / 128.0f, &sv, &cv);
    return mkpk(cv, sv);
}

// ---------------------------------------------------------------------------
// Fused setup: TF table everywhere; pos/weights in block 255, threads 0-31.
__global__ void __launch_bounds__(256) kSetup(const float* positions,
                                              const int* indices,
                                              const float* opr) {
    cudaTriggerProgrammaticLaunchCompletion();
    int idx = blockIdx.x * 256 + threadIdx.x;
    int i = idx >> 8, j = idx & 255;
    double fy = (double)((i < 128) ? i : i - 256) / (256.0 * 1.0e-8);
    double fx = (double)((j < 128) ? j : j - 256) / (256.0 * 1.0e-8);
    const double lam = 1.24e-10;
    double ax = lam * fx, ay = lam * fy;
    double arg = 1.0 - ax * ax - ay * ay;
    float tfx = 0.f, tfy = 0.f;
    if (arg > 0.0) {
        double ph = 2.0e-6 * (6.283185307179586 / lam) * sqrt(arg);
        tfx = (float)(cos(ph) * (1.0 / 65536.0));   // folds 2 inverse norms
        tfy = (float)(sin(ph) * (1.0 / 65536.0));
    }
    g_tf[idx] = mkpk(tfx, tfy);
    if (blockIdx.x == 255 && threadIdx.x < 32) {
        int b = threadIdx.x;
        int ix2 = indices[b];
        float py = positions[ix2 * 2 + 0], px = positions[ix2 * 2 + 1];
        float ry = rintf(py), rx = rintf(px);
        int iy = (int)ry, ix = (int)rx;
        iy = min(max(iy, 0), 768); ix = min(max(ix, 0), 768);
        g_ipos[b] = make_int2(iy, ix);
        g_frac[b] = make_float2(py - ry, px - rx);
        for (int k = 0; k < 4; k++) g_w[b][k] = opr[ix2 * 4 + k];
    }
}

// P0: 39 unique probe tiles (32 OPR + 7 shared modes), Fx (merged), store [kx][y].
__global__ void __launch_bounds__(256, 3) kP0(const float* probe) {
    __shared__ cpk buf[BUFSZ];
    int tid = threadIdx.x;
    const cpk n1 = mkpk(-1.f, -1.f);
    int u = blockIdx.y, row0 = blockIdx.x * 16;
    int line = tid >> 4, s = tid & 15;
    cpk ws = make_ws(s);
    pdl_sync_and_release();                  // need g_w from kSetup
    int y = row0 + line;
    const float2* p = (const float2*)probe;   // (4, 8, 256, 256) complex
    cpk v[16];
    if (u < 32) {
        float w0 = g_w[u][0], w1 = g_w[u][1], w2 = g_w[u][2], w3 = g_w[u][3];
        const float2* p0 = p + y * 256;
#pragma unroll
        for (int r = 0; r < 16; r++) {
            int x = s + 16 * r;
            float2 a = p0[x], b = p0[x + 524288], c = p0[x + 1048576], d = p0[x + 1572864];
            v[r] = mkpk(fmaf(w0, a.x, fmaf(w1, b.x, fmaf(w2, c.x, w3 * d.x))),
                        fmaf(w0, a.y, fmaf(w1, b.y, fmaf(w2, c.y, w3 * d.y))));
        }
    } else {
        int m = u - 31;
        const cpk* q = (const cpk*)probe + m * 65536 + y * 256;
#pragma unroll
        for (int r = 0; r < 16; r++) v[r] = q[s + 16 * r];
    }
    headA<false>(v, ws, n1);
#pragma unroll
    for (int pos = 0; pos < 16; pos++)
        buf[(dr4(pos) * 16 + line) * MROW + s] = v[pos];
    __syncthreads();
    cpk w[16];
    tail_read(w, buf + tid * MROW);
    fftDR<false>(w, n1);
    int nk2 = tid >> 4, nline = tid & 15;
    cpk* gout = g_g + u * 65536;
#pragma unroll
    for (int pos = 0; pos < 16; pos++)
        gout[(nk2 + 16 * dr4(pos)) * 256 + row0 + nline] = w[pos];
}

// P1a: Fy of the 39 unique probe tiles; store natural-order rows -> g_h.
__global__ void __launch_bounds__(256, 3) kP1a() {
    __shared__ cpk buf[BUFSZ];
    int tid = threadIdx.x;
    const cpk n1 = mkpk(-1.f, -1.f);
    int u = blockIdx.y, row0 = blockIdx.x * 16;
    int line = tid >> 4, s = tid & 15;
    cpk ws = make_ws(s);
    pdl_sync_and_release();                  // need g_g from kP0
    int kx = row0 + line;
    const cpk* src = g_g + u * 65536 + kx * 256;
    cpk v[16];
#pragma unroll
    for (int r = 0; r < 16; r++) v[r] = src[s + 16 * r];
    transformA<false>(v, buf + line * 256, ws, s, n1);
    cpk* gout = g_h + u * 65536 + kx * 256;
#pragma unroll
    for (int pos = 0; pos < 16; pos++)
        gout[s + 16 * dr4(pos)] = v[pos];      // natural ky order
}

// P1b: per (b,m): load Fy'd spectrum, x ramp (pre-scaled 1/65536),
//      Fy^-1 (merged), transposed store [y][kx] -> psiA.
__global__ void __launch_bounds__(256, 3) kP1b() {
    __shared__ cpk buf[BUFSZ];
    __shared__ cpk phb[16], phx[16], phc[2];
    int tid = threadIdx.x;
    int t = blockIdx.y, row0 = blockIdx.x * 16;
    int b = t >> 3, m = t & 7;
    int line = tid >> 4, s = tid & 15;
    cpk ws = make_ws(s);
    pdl_sync_and_release();                  // need g_frac + g_h
    float2 fr = g_frac[b];
    if (tid < 16) {                          // e^{-2pi i fy*s/256} / 65536
        float sv, cv; sincospif(-fr.x * (float)tid / 128.0f, &sv, &cv);
        phb[tid] = mkpk(cv * (1.0f / 65536.0f), sv * (1.0f / 65536.0f));
    } else if (tid < 32) {                   // e^{-2pi i fx*f(kx)} per line
        int l = tid - 16, kx = row0 + l;
        float fk = (float)((kx < 128) ? kx : kx - 256) * (1.0f / 256.0f);
        float sv, cv; sincospif(-2.0f * fr.y * fk, &sv, &cv);
        phx[l] = mkpk(cv, sv);
    } else if (tid == 32) {                  // step e^{-2pi i fy/16}
        float sv, cv; sincospif(-fr.x / 8.0f, &sv, &cv);
        phc[0] = mkpk(cv, sv);
    } else if (tid == 33) {                  // wrap corr e^{+2pi i fy}
        float sv, cv; sincospif(2.0f * fr.x, &sv, &cv);
        phc[1] = mkpk(cv, sv);
    }
    __syncthreads();
    const cpk n1 = mkpk(-1.f, -1.f);
    int kx = row0 + line;
    int u = (m == 0) ? b : 31 + m;
    const cpk* src = g_h + u * 65536 + kx * 256;
    cpk v[16];
#pragma unroll
    for (int r = 0; r < 16; r++) v[r] = src[s + 16 * r];   // natural ky order
    {   // ramp multiply at NATURAL positions: ky = s + 16*mm at slot mm
        cpk stp = phc[0], corr = phc[1];
        cpk base = cmulpp(phx[line], phb[s]);
        cpk s2 = cmulpp(stp, stp);
        cpk rg1 = cmulpp(s2, s2);            // step^4
        cpk rg2 = cmulpp(rg1, rg1);          // step^8
        cpk rg2c = cmulpp(rg2, corr);
        cpk rg3c = cmulpp(rg2c, rg1);        // step^12 * corr
        cpk b0 = base;
        cpk b1 = cmulpp(base, stp);
        cpk b2 = cmulpp(base, s2);
        cpk b3 = cmulpp(b1, s2);
#pragma unroll
        for (int mm = 0; mm < 16; mm++) {
            int bb = mm & 3, aa = mm >> 2;
            cpk f = (bb == 0) ? b0 : (bb == 1) ? b1 : (bb == 2) ? b2 : b3;
            v[mm] = cmulpp(v[mm], f);
            if (aa) {
                cpk g = (aa == 1) ? rg1 : (aa == 2) ? rg2c : rg3c;
                v[mm] = cmulpp(v[mm], g);
            }
        }
    }
    headA<true>(v, ws, n1);                  // fftDR + twiddle (DR slots)
#pragma unroll
    for (int pos = 0; pos < 16; pos++)
        buf[(dr4(pos) * 16 + line) * MROW + s] = v[pos];
    __syncthreads();
    cpk w[16];
    tail_read(w, buf + tid * MROW);
    fftDR<true>(w, n1);
    int nk2 = tid >> 4, nline = tid & 15;
    cpk* gout = g_psiA + t * 65536;
#pragma unroll
    for (int pos = 0; pos < 16; pos++)
        gout[(nk2 + 16 * dr4(pos)) * 256 + row0 + nline] = w[pos];
}

// kMod: Fx^-1 (full, unnorm), x object patch (L1-prefetched), Fx (merged).
__global__ void __launch_bounds__(256, 3) kMod(const float* object, int slice, int srcA) {
    __shared__ cpk buf[BUFSZ];
    int tid = threadIdx.x;
    const cpk n1 = mkpk(-1.f, -1.f);
    const cpk* sbuf = srcA ? g_psiA : g_psiB;
    cpk* dbuf = srcA ? g_psiB : g_psiA;
    int t = blockIdx.y, row0 = blockIdx.x * 16;
    int b = t >> 3;
    int line = tid >> 4, s = tid & 15;
    cpk ws = make_ws(s);
    pdl_sync_and_release();                  // need psi tiles (+ g_ipos)
    int y = row0 + line;
    int2 ip = g_ipos[b];
    const cpk* op = (const cpk*)object + slice * 1048576 + (ip.x + y) * 1024 + ip.y;
    pf_l1((const char*)op + s * 128);        // half-warp covers the row
    const cpk* sp = sbuf + t * 65536 + y * 256;
    cpk v[16];
#pragma unroll
    for (int r = 0; r < 16; r++) v[r] = sp[s + 16 * r];
    transformA<true>(v, buf + line * 256, ws, s, n1);
#pragma unroll
    for (int pos = 0; pos < 16; pos++)
        v[pos] = cmulpp(v[pos], op[s + 16 * dr4(pos)]);
    headB<false>(v, ws, n1);
    __syncthreads();
#pragma unroll
    for (int k2 = 0; k2 < 16; k2++)
        buf[(k2 * 16 + line) * MROW + s] = v[k2];
    __syncthreads();
    cpk w[16];
    tail_read(w, buf + tid * MROW);
    fftDR<false>(w, n1);
    int nk2 = tid >> 4, nline = tid & 15;
    cpk* gout = dbuf + t * 65536;
#pragma unroll
    for (int pos = 0; pos < 16; pos++)
        gout[(nk2 + 16 * dr4(pos)) * 256 + row0 + nline] = w[pos];
}

// kProp: Fy (full), x TF (L1-prefetched, pre-scaled), Fy^-1 (merged).
__global__ void __launch_bounds__(256, 3) kProp(int srcA) {
    __shared__ cpk buf[BUFSZ];
    int tid = threadIdx.x;
    const cpk n1 = mkpk(-1.f, -1.f);
    const cpk* sbuf = srcA ? g_psiA : g_psiB;
    cpk* dbuf = srcA ? g_psiB : g_psiA;
    int t = blockIdx.y, row0 = blockIdx.x * 16;
    int line = tid >> 4, s = tid & 15;
    cpk ws = make_ws(s);
    pdl_sync_and_release();                  // need psi tiles
    int kx = row0 + line;
    const cpk* tfp = g_tf + kx * 256;        // TF symmetric in (ky,kx)
    pf_l1((const char*)tfp + s * 128);
    const cpk* sp = sbuf + t * 65536 + kx * 256;
    cpk v[16];
#pragma unroll
    for (int r = 0; r < 16; r++) v[r] = sp[s + 16 * r];
    transformA<false>(v, buf + line * 256, ws, s, n1);
#pragma unroll
    for (int pos = 0; pos < 16; pos++)
        v[pos] = cmulpp(v[pos], tfp[s + 16 * dr4(pos)]);
    headB<true>(v, ws, n1);
    __syncthreads();
#pragma unroll
    for (int k2 = 0; k2 < 16; k2++)
        buf[(k2 * 16 + line) * MROW + s] = v[k2];
    __syncthreads();
    cpk w[16];
    tail_read(w, buf + tid * MROW);
    fftDR<true>(w, n1);
    int nk2 = tid >> 4, nline = tid & 15;
    cpk* gout = dbuf + t * 65536;
#pragma unroll
    for (int pos = 0; pos < 16; pos++)
        gout[(nk2 + 16 * dr4(pos)) * 256 + row0 + nline] = w[pos];
}

// P9 (split): final Fy (merged) for 2 modes per CTA (blockIdx.z = group),
// |.|^2 accumulated, fftshift remap, raw partials -> g_part.
__global__ void __launch_bounds__(256, 3) kFinal2() {
    __shared__ cpk buf[BUFSZ];
    int tid = threadIdx.x;
    const cpk n1 = mkpk(-1.f, -1.f);
    int bb = blockIdx.y, row0 = blockIdx.x * 16, z = blockIdx.z;
    int line = tid >> 4, s = tid & 15;
    cpk ws = make_ws(s);
    pdl_sync_and_release();                  // need psiB
    int kx = row0 + line;
    float acc[16];
#pragma unroll
    for (int r = 0; r < 16; r++) acc[r] = 0.f;
    const cpk* base = g_psiB + ((size_t)bb * 8 + z * 2) * 65536 + kx * 256;
    pf_l1((const char*)base + s * 128);      // first mode's row
    for (int m = 0; m < 2; m++) {
        if (m) __syncthreads();              // readers of prev iter done
        const cpk* sp = base + m * 65536;
        cpk v[16];
#pragma unroll
        for (int r = 0; r < 16; r++) v[r] = sp[s + 16 * r];
        if (m < 1)                           // prefetch next mode's row
            pf_l1((const char*)(sp + 65536) + s * 128);
        headA<false>(v, ws, n1);
#pragma unroll
        for (int pos = 0; pos < 16; pos++)
            buf[(dr4(pos) * 16 + line) * MROW + s] = v[pos];
        __syncthreads();
        cpk w[16];
        tail_read(w, buf + tid * MROW);
        fftDR<false>(w, n1);
#pragma unroll
        for (int pos = 0; pos < 16; pos++) {
            float x, y; unpk(w[pos], x, y);
            acc[pos] = fmaf(x, x, fmaf(y, y, acc[pos]));
        }
    }
    int nk2 = tid >> 4, nline = tid & 15;
    int xo = (row0 + nline + 128) & 255;                 // fftshift cols
    float* op = g_part + ((size_t)z * 32 + bb) * 65536;
#pragma unroll
    for (int pos = 0; pos < 16; pos++) {
        int ky = nk2 + 16 * dr4(pos);
        int yo = (ky + 128) & 255;                       // fftshift rows
        op[yo * 256 + xo] = acc[pos];                    // raw partial
    }
}

// Deterministic fixed-order reduction of the 4 mode-group partials + ortho norm.
__global__ void __launch_bounds__(256) kReduce(float* out) {
    pdl_sync_and_release();                  // need g_part
    int idx = blockIdx.x * 256 + threadIdx.x;            // float4 index
    const float4* p0 = (const float4*)g_part;
    const float4* p1 = p0 + 524288;                      // 32*65536/4
    const float4* p2 = p1 + 524288;
    const float4* p3 = p2 + 524288;
    float4 a = p0[idx], b = p1[idx], c = p2[idx], d = p3[idx];
    float4 r;
    r.x = (a.x + b.x + c.x + d.x) * (1.0f / 65536.0f);
    r.y = (a.y + b.y + c.y + d.y) * (1.0f / 65536.0f);
    r.z = (a.z + b.z + c.z + d.z) * (1.0f / 65536.0f);
    r.w = (a.w + b.w + c.w + d.w) * (1.0f / 65536.0f);
    ((float4*)out)[idx] = r;
}

// ---------------------------------------------------------------------------
// Launch helper: programmatic stream serialization (PDL) on every kernel.
template <typename F, typename... Args>
static inline void launch_pdl(F f, dim3 grid, dim3 block, Args... args) {
    cudaLaunchConfig_t cfg = {};
    cfg.gridDim = grid;
    cfg.blockDim = block;
    cudaLaunchAttribute at[1];
    at[0].id = cudaLaunchAttributeProgrammaticStreamSerialization;
    at[0].val.programmaticStreamSerializationAllowed = 1;
    cfg.attrs = at;
    cfg.numAttrs = 1;
    cudaLaunchKernelEx(&cfg, f, args...);
}

extern "C" void kernel_launch(void* const* d_in, const int* in_sizes, int n_in,
                              void* d_out, int out_size) {
    const float* object = nullptr;    // (4,1024,1024,2)  -> 8388608
    const float* probe = nullptr;     // (4,8,256,256,2)  -> 4194304
    const float* opr = nullptr;       // (512,4)          -> 2048
    const float* positions = nullptr; // (512,2)          -> 1024
    const int*   indices = nullptr;   // (32,)            -> 32
    for (int i = 0; i < n_in; i++) {
        switch (in_sizes[i]) {
            case 8388608: object    = (const float*)d_in[i]; break;
            case 4194304: probe     = (const float*)d_in[i]; break;
            case 2048:    opr       = (const float*)d_in[i]; break;
            case 1024:    positions = (const float*)d_in[i]; break;
            case 32:      indices   = (const int*)d_in[i];   break;
        }
    }
    float* out = (float*)d_out;

    launch_pdl(kSetup, dim3(256), dim3(256), positions, indices, opr);
    launch_pdl(kP0, dim3(16, 39), dim3(256), probe);
    launch_pdl(kP1a, dim3(16, 39), dim3(256));           // g_g -> g_h
    launch_pdl(kP1b, dim3(16, 256), dim3(256));          // -> psiA
    launch_pdl(kMod, dim3(16, 256), dim3(256), object, 0, 1);
    launch_pdl(kProp, dim3(16, 256), dim3(256), 0);
    launch_pdl(kMod, dim3(16, 256), dim3(256), object, 1, 1);
    launch_pdl(kProp, dim3(16, 256), dim3(256), 0);
    launch_pdl(kMod, dim3(16, 256), dim3(256), object, 2, 1);
    launch_pdl(kProp, dim3(16, 256), dim3(256), 0);
    launch_pdl(kMod, dim3(16, 256), dim3(256), object, 3, 1);
    launch_pdl(kFinal2, dim3(16, 32, 4), dim3(256));     // B -> g_part
    launch_pdl(kReduce, dim3(2048), dim3(256), out);     // sum + norm
}

// round 17
// speedup vs baseline: 1.0482x; 1.0482x over previous
#include <cuda_runtime.h>
#include <cuda_bf16.h>

// ---------------------------------------------------------------------------
// Ptychography forward model (sm_103a).  Fused 1-D FFT passes; FFT-256 =
// 16x16 four-step in packed fp32x2; in-place digit-reversed FFT-16; merged
// final exchange+transpose; tree cross-twiddles; kP1 split; L1 prefetches;
// kFinal mode-split + deterministic reduce; PDL chain.
// R17: heavy kernels use 128-thread CTAs (8 lines) -> 7 CTAs/SM (28 warps,
// +17% occupancy) instead of 3x256 (24 warps, RF-quantization limited).
// ---------------------------------------------------------------------------

typedef unsigned long long cpk;   // packed complex: lo=re, hi=im (f32x2)

// ---- static device scratch ----
__device__ cpk   g_g[39 * 65536];        // probe tiles after first Fx
__device__ cpk   g_h[39 * 65536];        // probe tiles after Fy (spectrum)
__device__ cpk   g_psiA[256 * 65536];    // ping (128 MB)
__device__ cpk   g_psiB[256 * 65536];    // pong (128 MB)
__device__ cpk   g_tf[65536];            // angular-spectrum TF (pre-scaled 1/65536)
__device__ float g_part[4 * 32 * 65536]; // per-mode-group intensity partials
__device__ int2  g_ipos[32];
__device__ float2 g_frac[32];
__device__ float g_w[32][4];

// ---- packed complex helpers ----
__device__ __forceinline__ cpk mkpk(float x, float y) {
    cpk r; asm("mov.b64 %0, {%1, %2};" : "=l"(r) : "f"(x), "f"(y)); return r;
}
__device__ __forceinline__ void unpk(cpk a, float& x, float& y) {
    asm("mov.b64 {%0, %1}, %2;" : "=f"(x), "=f"(y) : "l"(a));
}
__device__ __forceinline__ cpk addpk(cpk a, cpk b) {
    cpk r; asm("add.rn.f32x2 %0, %1, %2;" : "=l"(r) : "l"(a), "l"(b)); return r;
}
__device__ __forceinline__ cpk fmapk(cpk a, cpk b, cpk c) {
    cpk r; asm("fma.rn.f32x2 %0, %1, %2, %3;" : "=l"(r) : "l"(a), "l"(b), "l"(c)); return r;
}
__device__ __forceinline__ cpk subpk(cpk a, cpk b, cpk n1) {   // a - b
    return fmapk(b, n1, a);
}
__device__ __forceinline__ cpk cmulpp(cpk a, cpk b) {          // a * b
    float ax, ay, bx, by; unpk(a, ax, ay); unpk(b, bx, by);
    return mkpk(fmaf(ax, bx, -(ay * by)), fmaf(ax, by, ay * bx));
}
__device__ __forceinline__ cpk cmulcc(cpk a, cpk b) {          // a * conj(b)
    float ax, ay, bx, by; unpk(a, ax, ay); unpk(b, bx, by);
    return mkpk(fmaf(ax, bx, ay * by), fmaf(ay, bx, -(ax * by)));
}
__device__ __forceinline__ cpk cmulk(cpk a, float bx, float by) { // a * (bx+i by)
    float ax, ay; unpk(a, ax, ay);
    return mkpk(fmaf(ax, bx, -(ay * by)), fmaf(ax, by, ay * bx));
}

__device__ __forceinline__ void pf_l1(const void* p) {
    asm volatile("prefetch.global.L1 [%0];" :: "l"(p));
}

// PDL: wait for predecessor's memory, then release our successor's launch.
__device__ __forceinline__ void pdl_sync_and_release() {
    cudaGridDependencySynchronize();
    cudaTriggerProgrammaticLaunchCompletion();
}

// base-4 digit reversal of 4-bit index (involution)
__device__ __forceinline__ constexpr int dr4(int p) { return ((p & 3) << 2) | (p >> 2); }

template<bool INV>
__device__ __forceinline__ void btf4p(cpk& a, cpk& b, cpk& c, cpk& d, cpk n1) {
    cpk t0 = addpk(a, c), t1 = subpk(a, c, n1);
    cpk t2 = addpk(b, d), t3 = subpk(b, d, n1);
    a = addpk(t0, t2); c = subpk(t0, t2, n1);
    float x, y; unpk(t3, x, y);
    cpk u = INV ? mkpk(-y, x) : mkpk(y, -x);   // -/+ i*t3
    b = addpk(t1, u); d = subpk(t1, u, n1);
}

#define TWK(q, arr_c, arr_s) arr_c[q], (INV ? -arr_s[q] : arr_s[q])

// in-place 16-pt DFT, NATURAL input -> DIGIT-REVERSED output
template<bool INV>
__device__ __forceinline__ void fftDR(cpk* v, cpk n1) {
    const float C1[4] = { 1.f, 0.92387953f, 0.70710678f, 0.38268343f };
    const float S1[4] = { 0.f, -0.38268343f, -0.70710678f, -0.92387953f };
    const float C2[4] = { 1.f, 0.70710678f, 0.f, -0.70710678f };
    const float S2[4] = { 0.f, -0.70710678f, -1.f, -0.70710678f };
    const float C3[4] = { 1.f, 0.38268343f, -0.70710678f, -0.92387953f };
    const float S3[4] = { 0.f, -0.92387953f, -0.70710678f, 0.38268343f };
#pragma unroll
    for (int a = 0; a < 4; a++)
        btf4p<INV>(v[a], v[a + 4], v[a + 8], v[a + 12], n1);
#pragma unroll
    for (int q = 0; q < 4; q++) {
        if (q) {
            v[4 * q + 1] = cmulk(v[4 * q + 1], TWK(q, C1, S1));
            v[4 * q + 2] = cmulk(v[4 * q + 2], TWK(q, C2, S2));
            v[4 * q + 3] = cmulk(v[4 * q + 3], TWK(q, C3, S3));
        }
        btf4p<INV>(v[4 * q], v[4 * q + 1], v[4 * q + 2], v[4 * q + 3], n1);
    }
}

// in-place 16-pt DFT, DIGIT-REVERSED input -> NATURAL output
template<bool INV>
__device__ __forceinline__ void fftRD(cpk* v, cpk n1) {
    const float C1[4] = { 1.f, 0.92387953f, 0.70710678f, 0.38268343f };
    const float S1[4] = { 0.f, -0.38268343f, -0.70710678f, -0.92387953f };
    const float C2[4] = { 1.f, 0.70710678f, 0.f, -0.70710678f };
    const float S2[4] = { 0.f, -0.70710678f, -1.f, -0.70710678f };
    const float C3[4] = { 1.f, 0.38268343f, -0.70710678f, -0.92387953f };
    const float S3[4] = { 0.f, -0.92387953f, -0.70710678f, 0.38268343f };
#pragma unroll
    for (int a = 0; a < 4; a++)
        btf4p<INV>(v[4 * a], v[4 * a + 1], v[4 * a + 2], v[4 * a + 3], n1);
#pragma unroll
    for (int q = 0; q < 4; q++) {
        if (q) {
            v[q + 4]  = cmulk(v[q + 4],  TWK(q, C1, S1));
            v[q + 8]  = cmulk(v[q + 8],  TWK(q, C2, S2));
            v[q + 12] = cmulk(v[q + 12], TWK(q, C3, S3));
        }
        btf4p<INV>(v[q], v[q + 4], v[q + 8], v[q + 12], n1);
    }
}

// Tree-structured cross-twiddle: v[k] *= W^{s*k}, k = 4a+b.
template<bool INV, bool DRIDX>
__device__ __forceinline__ void twiddle16(cpk* v, cpk ws) {
    cpk w2 = cmulpp(ws, ws);
    cpk w3 = cmulpp(w2, ws);
    cpk g1 = cmulpp(w2, w2);        // W^4
    cpk g2 = cmulpp(g1, g1);        // W^8
    cpk g3 = cmulpp(g2, g1);        // W^12
#pragma unroll
    for (int k = 1; k < 16; k++) {
        int pos = DRIDX ? dr4(k) : k;
        int b = k & 3, a = k >> 2;
        if (b) {
            cpk wb = (b == 1) ? ws : (b == 2) ? w2 : w3;
            v[pos] = INV ? cmulcc(v[pos], wb) : cmulpp(v[pos], wb);
        }
        if (a) {
            cpk g = (a == 1) ? g1 : (a == 2) ? g2 : g3;
            v[pos] = INV ? cmulcc(v[pos], g) : cmulpp(v[pos], g);
        }
    }
}

// Full 256-pt transform, natural in -> DR out.  Line-private xch region.
template<bool INV>
__device__ __forceinline__ void transformA(cpk* v, cpk* xch, cpk ws,
                                           int s, cpk n1) {
    fftDR<INV>(v, n1);
    twiddle16<INV, true>(v, ws);
    __syncwarp();
#pragma unroll
    for (int pos = 0; pos < 16; pos++)
        xch[s * 16 + ((dr4(pos) + s) & 15)] = v[pos];
    __syncwarp();
#pragma unroll
    for (int a = 0; a < 16; a++) v[a] = xch[a * 16 + ((s + a) & 15)];
    fftDR<INV>(v, n1);
}

// Heads of merged transforms: fft + tree twiddle, no exchange.
template<bool INV>
__device__ __forceinline__ void headB(cpk* v, cpk ws, cpk n1) {
    fftRD<INV>(v, n1);
    twiddle16<INV, false>(v, ws);
}
template<bool INV>
__device__ __forceinline__ void headA(cpk* v, cpk ws, cpk n1) {
    fftDR<INV>(v, n1);
    twiddle16<INV, true>(v, ws);
}

#define MROW 18
#define BUFSZ (256 * MROW)            // 16-line kernels (kP0, kP1a)
#define LPB 8                         // lines per block, heavy kernels
#define HBUF (16 * LPB * MROW)        // 2304 cpk (also >= LPB*256 xch)

// Vectorized merged-tail read: 16 consecutive cpk as 8 x LDS.128.
__device__ __forceinline__ void tail_read(cpk* w, const cpk* row) {
    const ulonglong2* bp = (const ulonglong2*)row;
#pragma unroll
    for (int a = 0; a < 8; a++) {
        ulonglong2 t = bp[a];
        w[2 * a] = t.x; w[2 * a + 1] = t.y;
    }
}

// per-thread W256^s
__device__ __forceinline__ cpk make_ws(int s) {
    float sv, cv; sincospif(-(float)s / 128.0f, &sv, &cv);
    return mkpk(cv, sv);
}

// ---------------------------------------------------------------------------
// Fused setup: TF table everywhere; pos/weights in block 255, threads 0-31.
__global__ void __launch_bounds__(256) kSetup(const float* positions,
                                              const int* indices,
                                              const float* opr) {
    cudaTriggerProgrammaticLaunchCompletion();
    int idx = blockIdx.x * 256 + threadIdx.x;
    int i = idx >> 8, j = idx & 255;
    double fy = (double)((i < 128) ? i : i - 256) / (256.0 * 1.0e-8);
    double fx = (double)((j < 128) ? j : j - 256) / (256.0 * 1.0e-8);
    const double lam = 1.24e-10;
    double ax = lam * fx, ay = lam * fy;
    double arg = 1.0 - ax * ax - ay * ay;
    float tfx = 0.f, tfy = 0.f;
    if (arg > 0.0) {
        double ph = 2.0e-6 * (6.283185307179586 / lam) * sqrt(arg);
        tfx = (float)(cos(ph) * (1.0 / 65536.0));   // folds 2 inverse norms
        tfy = (float)(sin(ph) * (1.0 / 65536.0));
    }
    g_tf[idx] = mkpk(tfx, tfy);
    if (blockIdx.x == 255 && threadIdx.x < 32) {
        int b = threadIdx.x;
        int ix2 = indices[b];
        float py = positions[ix2 * 2 + 0], px = positions[ix2 * 2 + 1];
        float ry = rintf(py), rx = rintf(px);
        int iy = (int)ry, ix = (int)rx;
        iy = min(max(iy, 0), 768); ix = min(max(ix, 0), 768);
        g_ipos[b] = make_int2(iy, ix);
        g_frac[b] = make_float2(py - ry, px - rx);
        for (int k = 0; k < 4; k++) g_w[b][k] = opr[ix2 * 4 + k];
    }
}

// P0: 39 unique probe tiles, Fx (merged), store [kx][y].  16 lines.
__global__ void __launch_bounds__(256, 3) kP0(const float* probe) {
    __shared__ cpk buf[BUFSZ];
    int tid = threadIdx.x;
    const cpk n1 = mkpk(-1.f, -1.f);
    int u = blockIdx.y, row0 = blockIdx.x * 16;
    int line = tid >> 4, s = tid & 15;
    cpk ws = make_ws(s);
    pdl_sync_and_release();                  // need g_w from kSetup
    int y = row0 + line;
    const float2* p = (const float2*)probe;   // (4, 8, 256, 256) complex
    cpk v[16];
    if (u < 32) {
        float w0 = g_w[u][0], w1 = g_w[u][1], w2 = g_w[u][2], w3 = g_w[u][3];
        const float2* p0 = p + y * 256;
#pragma unroll
        for (int r = 0; r < 16; r++) {
            int x = s + 16 * r;
            float2 a = p0[x], b = p0[x + 524288], c = p0[x + 1048576], d = p0[x + 1572864];
            v[r] = mkpk(fmaf(w0, a.x, fmaf(w1, b.x, fmaf(w2, c.x, w3 * d.x))),
                        fmaf(w0, a.y, fmaf(w1, b.y, fmaf(w2, c.y, w3 * d.y))));
        }
    } else {
        int m = u - 31;
        const cpk* q = (const cpk*)probe + m * 65536 + y * 256;
#pragma unroll
        for (int r = 0; r < 16; r++) v[r] = q[s + 16 * r];
    }
    headA<false>(v, ws, n1);
#pragma unroll
    for (int pos = 0; pos < 16; pos++)
        buf[(dr4(pos) * 16 + line) * MROW + s] = v[pos];
    __syncthreads();
    cpk w[16];
    tail_read(w, buf + tid * MROW);
    fftDR<false>(w, n1);
    int nk2 = tid >> 4, nline = tid & 15;
    cpk* gout = g_g + u * 65536;
#pragma unroll
    for (int pos = 0; pos < 16; pos++)
        gout[(nk2 + 16 * dr4(pos)) * 256 + row0 + nline] = w[pos];
}

// P1a: Fy of 39 unique probe tiles; store natural-order rows -> g_h.  16 lines.
__global__ void __launch_bounds__(256, 3) kP1a() {
    __shared__ cpk buf[BUFSZ];
    int tid = threadIdx.x;
    const cpk n1 = mkpk(-1.f, -1.f);
    int u = blockIdx.y, row0 = blockIdx.x * 16;
    int line = tid >> 4, s = tid & 15;
    cpk ws = make_ws(s);
    pdl_sync_and_release();                  // need g_g from kP0
    int kx = row0 + line;
    const cpk* src = g_g + u * 65536 + kx * 256;
    cpk v[16];
#pragma unroll
    for (int r = 0; r < 16; r++) v[r] = src[s + 16 * r];
    transformA<false>(v, buf + line * 256, ws, s, n1);
    cpk* gout = g_h + u * 65536 + kx * 256;
#pragma unroll
    for (int pos = 0; pos < 16; pos++)
        gout[s + 16 * dr4(pos)] = v[pos];      // natural ky order
}

// P1b: per (b,m): load Fy'd spectrum, x ramp, Fy^-1 (merged).  8 lines.
__global__ void __launch_bounds__(128, 7) kP1b() {
    __shared__ cpk buf[HBUF];
    __shared__ cpk phb[16], phx[LPB], phc[2];
    int tid = threadIdx.x;
    int t = blockIdx.y, row0 = blockIdx.x * LPB;
    int b = t >> 3, m = t & 7;
    int line = tid >> 4, s = tid & 15;
    cpk ws = make_ws(s);
    pdl_sync_and_release();                  // need g_frac + g_h
    float2 fr = g_frac[b];
    if (tid < 16) {                          // e^{-2pi i fy*s/256} / 65536
        float sv, cv; sincospif(-fr.x * (float)tid / 128.0f, &sv, &cv);
        phb[tid] = mkpk(cv * (1.0f / 65536.0f), sv * (1.0f / 65536.0f));
    } else if (tid < 16 + LPB) {             // e^{-2pi i fx*f(kx)} per line
        int l = tid - 16, kx = row0 + l;
        float fk = (float)((kx < 128) ? kx : kx - 256) * (1.0f / 256.0f);
        float sv, cv; sincospif(-2.0f * fr.y * fk, &sv, &cv);
        phx[l] = mkpk(cv, sv);
    } else if (tid == 32) {                  // step e^{-2pi i fy/16}
        float sv, cv; sincospif(-fr.x / 8.0f, &sv, &cv);
        phc[0] = mkpk(cv, sv);
    } else if (tid == 33) {                  // wrap corr e^{+2pi i fy}
        float sv, cv; sincospif(2.0f * fr.x, &sv, &cv);
        phc[1] = mkpk(cv, sv);
    }
    __syncthreads();
    const cpk n1 = mkpk(-1.f, -1.f);
    int kx = row0 + line;
    int u = (m == 0) ? b : 31 + m;
    const cpk* src = g_h + u * 65536 + kx * 256;
    cpk v[16];
#pragma unroll
    for (int r = 0; r < 16; r++) v[r] = src[s + 16 * r];   // natural ky order
    {   // ramp multiply at NATURAL positions: ky = s + 16*mm at slot mm
        cpk stp = phc[0], corr = phc[1];
        cpk base = cmulpp(phx[line], phb[s]);
        cpk s2 = cmulpp(stp, stp);
        cpk rg1 = cmulpp(s2, s2);            // step^4
        cpk rg2 = cmulpp(rg1, rg1);          // step^8
        cpk rg2c = cmulpp(rg2, corr);
        cpk rg3c = cmulpp(rg2c, rg1);        // step^12 * corr
        cpk b0 = base;
        cpk b1 = cmulpp(base, stp);
        cpk b2 = cmulpp(base, s2);
        cpk b3 = cmulpp(b1, s2);
#pragma unroll
        for (int mm = 0; mm < 16; mm++) {
            int bb = mm & 3, aa = mm >> 2;
            cpk f = (bb == 0) ? b0 : (bb == 1) ? b1 : (bb == 2) ? b2 : b3;
            v[mm] = cmulpp(v[mm], f);
            if (aa) {
                cpk g = (aa == 1) ? rg1 : (aa == 2) ? rg2c : rg3c;
                v[mm] = cmulpp(v[mm], g);
            }
        }
    }
    headA<true>(v, ws, n1);                  // fftDR + twiddle (DR slots)
#pragma unroll
    for (int pos = 0; pos < 16; pos++)
        buf[(dr4(pos) * LPB + line) * MROW + s] = v[pos];
    __syncthreads();
    cpk w[16];
    tail_read(w, buf + tid * MROW);
    fftDR<true>(w, n1);
    int nk2 = tid >> 3, nline = tid & 7;
    cpk* gout = g_psiA + t * 65536;
#pragma unroll
    for (int pos = 0; pos < 16; pos++)
        gout[(nk2 + 16 * dr4(pos)) * 256 + row0 + nline] = w[pos];
}

// kMod: Fx^-1 (full, unnorm), x object patch (L1-prefetched), Fx (merged).
__global__ void __launch_bounds__(128, 7) kMod(const float* object, int slice, int srcA) {
    __shared__ cpk buf[HBUF];
    int tid = threadIdx.x;
    const cpk n1 = mkpk(-1.f, -1.f);
    const cpk* sbuf = srcA ? g_psiA : g_psiB;
    cpk* dbuf = srcA ? g_psiB : g_psiA;
    int t = blockIdx.y, row0 = blockIdx.x * LPB;
    int b = t >> 3;
    int line = tid >> 4, s = tid & 15;
    cpk ws = make_ws(s);
    pdl_sync_and_release();                  // need psi tiles (+ g_ipos)
    int y = row0 + line;
    int2 ip = g_ipos[b];
    const cpk* op = (const cpk*)object + slice * 1048576 + (ip.x + y) * 1024 + ip.y;
    pf_l1((const char*)op + s * 128);        // half-warp covers the row
    const cpk* sp = sbuf + t * 65536 + y * 256;
    cpk v[16];
#pragma unroll
    for (int r = 0; r < 16; r++) v[r] = sp[s + 16 * r];
    transformA<true>(v, buf + line * 256, ws, s, n1);
#pragma unroll
    for (int pos = 0; pos < 16; pos++)
        v[pos] = cmulpp(v[pos], op[s + 16 * dr4(pos)]);
    headB<false>(v, ws, n1);
    __syncthreads();
#pragma unroll
    for (int k2 = 0; k2 < 16; k2++)
        buf[(k2 * LPB + line) * MROW + s] = v[k2];
    __syncthreads();
    cpk w[16];
    tail_read(w, buf + tid * MROW);
    fftDR<false>(w, n1);
    int nk2 = tid >> 3, nline = tid & 7;
    cpk* gout = dbuf + t * 65536;
#pragma unroll
    for (int pos = 0; pos < 16; pos++)
        gout[(nk2 + 16 * dr4(pos)) * 256 + row0 + nline] = w[pos];
}

// kProp: Fy (full), x TF (L1-prefetched, pre-scaled), Fy^-1 (merged).
__global__ void __launch_bounds__(128, 7) kProp(int srcA) {
    __shared__ cpk buf[HBUF];
    int tid = threadIdx.x;
    const cpk n1 = mkpk(-1.f, -1.f);
    const cpk* sbuf = srcA ? g_psiA : g_psiB;
    cpk* dbuf = srcA ? g_psiB : g_psiA;
    int t = blockIdx.y, row0 = blockIdx.x * LPB;
    int line = tid >> 4, s = tid & 15;
    cpk ws = make_ws(s);
    pdl_sync_and_release();                  // need psi tiles
    int kx = row0 + line;
    const cpk* tfp = g_tf + kx * 256;        // TF symmetric in (ky,kx)
    pf_l1((const char*)tfp + s * 128);
    const cpk* sp = sbuf + t * 65536 + kx * 256;
    cpk v[16];
#pragma unroll
    for (int r = 0; r < 16; r++) v[r] = sp[s + 16 * r];
    transformA<false>(v, buf + line * 256, ws, s, n1);
#pragma unroll
    for (int pos = 0; pos < 16; pos++)
        v[pos] = cmulpp(v[pos], tfp[s + 16 * dr4(pos)]);
    headB<true>(v, ws, n1);
    __syncthreads();
#pragma unroll
    for (int k2 = 0; k2 < 16; k2++)
        buf[(k2 * LPB + line) * MROW + s] = v[k2];
    __syncthreads();
    cpk w[16];
    tail_read(w, buf + tid * MROW);
    fftDR<true>(w, n1);
    int nk2 = tid >> 3, nline = tid & 7;
    cpk* gout = dbuf + t * 65536;
#pragma unroll
    for (int pos = 0; pos < 16; pos++)
        gout[(nk2 + 16 * dr4(pos)) * 256 + row0 + nline] = w[pos];
}

// P9 (split): final Fy (merged) for 2 modes per CTA, |.|^2, fftshift remap.
__global__ void __launch_bounds__(128, 7) kFinal2() {
    __shared__ cpk buf[HBUF];
    int tid = threadIdx.x;
    const cpk n1 = mkpk(-1.f, -1.f);
    int bb = blockIdx.y, row0 = blockIdx.x * LPB, z = blockIdx.z;
    int line = tid >> 4, s = tid & 15;
    cpk ws = make_ws(s);
    pdl_sync_and_release();                  // need psiB
    int kx = row0 + line;
    float acc[16];
#pragma unroll
    for (int r = 0; r < 16; r++) acc[r] = 0.f;
    const cpk* base = g_psiB + ((size_t)bb * 8 + z * 2) * 65536 + kx * 256;
    pf_l1((const char*)base + s * 128);      // first mode's row
    for (int m = 0; m < 2; m++) {
        if (m) __syncthreads();              // readers of prev iter done
        const cpk* sp = base + m * 65536;
        cpk v[16];
#pragma unroll
        for (int r = 0; r < 16; r++) v[r] = sp[s + 16 * r];
        if (m < 1)                           // prefetch next mode's row
            pf_l1((const char*)(sp + 65536) + s * 128);
        headA<false>(v, ws, n1);
#pragma unroll
        for (int pos = 0; pos < 16; pos++)
            buf[(dr4(pos) * LPB + line) * MROW + s] = v[pos];
        __syncthreads();
        cpk w[16];
        tail_read(w, buf + tid * MROW);
        fftDR<false>(w, n1);
#pragma unroll
        for (int pos = 0; pos < 16; pos++) {
            float x, y; unpk(w[pos], x, y);
            acc[pos] = fmaf(x, x, fmaf(y, y, acc[pos]));
        }
    }
    int nk2 = tid >> 3, nline = tid & 7;
    int xo = (row0 + nline + 128) & 255;                 // fftshift cols
    float* op = g_part + ((size_t)z * 32 + bb) * 65536;
#pragma unroll
    for (int pos = 0; pos < 16; pos++) {
        int ky = nk2 + 16 * dr4(pos);
        int yo = (ky + 128) & 255;                       // fftshift rows
        op[yo * 256 + xo] = acc[pos];                    // raw partial
    }
}

// Deterministic fixed-order reduction of the 4 mode-group partials + ortho norm.
__global__ void __launch_bounds__(256) kReduce(float* out) {
    pdl_sync_and_release();                  // need g_part
    int idx = blockIdx.x * 256 + threadIdx.x;            // float4 index
    const float4* p0 = (const float4*)g_part;
    const float4* p1 = p0 + 524288;                      // 32*65536/4
    const float4* p2 = p1 + 524288;
    const float4* p3 = p2 + 524288;
    float4 a = p0[idx], b = p1[idx], c = p2[idx], d = p3[idx];
    float4 r;
    r.x = (a.x + b.x + c.x + d.x) * (1.0f / 65536.0f);
    r.y = (a.y + b.y + c.y + d.y) * (1.0f / 65536.0f);
    r.z = (a.z + b.z + c.z + d.z) * (1.0f / 65536.0f);
    r.w = (a.w + b.w + c.w + d.w) * (1.0f / 65536.0f);
    ((float4*)out)[idx] = r;
}

// ---------------------------------------------------------------------------
// Launch helper: programmatic stream serialization (PDL) on every kernel.
template <typename F, typename... Args>
static inline void launch_pdl(F f, dim3 grid, dim3 block, Args... args) {
    cudaLaunchConfig_t cfg = {};
    cfg.gridDim = grid;
    cfg.blockDim = block;
    cudaLaunchAttribute at[1];
    at[0].id = cudaLaunchAttributeProgrammaticStreamSerialization;
    at[0].val.programmaticStreamSerializationAllowed = 1;
    cfg.attrs = at;
    cfg.numAttrs = 1;
    cudaLaunchKernelEx(&cfg, f, args...);
}

extern "C" void kernel_launch(void* const* d_in, const int* in_sizes, int n_in,
                              void* d_out, int out_size) {
    const float* object = nullptr;    // (4,1024,1024,2)  -> 8388608
    const float* probe = nullptr;     // (4,8,256,256,2)  -> 4194304
    const float* opr = nullptr;       // (512,4)          -> 2048
    const float* positions = nullptr; // (512,2)          -> 1024
    const int*   indices = nullptr;   // (32,)            -> 32
    for (int i = 0; i < n_in; i++) {
        switch (in_sizes[i]) {
            case 8388608: object    = (const float*)d_in[i]; break;
            case 4194304: probe     = (const float*)d_in[i]; break;
            case 2048:    opr       = (const float*)d_in[i]; break;
            case 1024:    positions = (const float*)d_in[i]; break;
            case 32:      indices   = (const int*)d_in[i];   break;
        }
    }
    float* out = (float*)d_out;

    launch_pdl(kSetup, dim3(256), dim3(256), positions, indices, opr);
    launch_pdl(kP0, dim3(16, 39), dim3(256), probe);
    launch_pdl(kP1a, dim3(16, 39), dim3(256));           // g_g -> g_h
    launch_pdl(kP1b, dim3(32, 256), dim3(128));          // -> psiA
    launch_pdl(kMod, dim3(32, 256), dim3(128), object, 0, 1);
    launch_pdl(kProp, dim3(32, 256), dim3(128), 0);
    launch_pdl(kMod, dim3(32, 256), dim3(128), object, 1, 1);
    launch_pdl(kProp, dim3(32, 256), dim3(128), 0);
    launch_pdl(kMod, dim3(32, 256), dim3(128), object, 2, 1);
    launch_pdl(kProp, dim3(32, 256), dim3(128), 0);
    launch_pdl(kMod, dim3(32, 256), dim3(128), object, 3, 1);
    launch_pdl(kFinal2, dim3(32, 32, 4), dim3(128));     // B -> g_part
    launch_pdl(kReduce, dim3(2048), dim3(256), out);     // sum + norm
}